// round 1
// baseline (speedup 1.0000x reference)
#include <cuda_runtime.h>

// CenterLoss collapses: mask is one-hot on labels, so only distmat[i, labels[i]]
// survives; all other (B*C - B) masked zeros clamp to 1e-12 (a constant).
// loss = ( sum_i clamp(||x_i - c_{labels[i]}||^2, 1e-12, 1e12) + (B*C-B)*1e-12 ) / B

#define BATCH     1024
#define NUM_CLASS 100000
#define FEAT      128

#define NBLK 128   // 128 blocks * 8 warps = 1024 warps = 1 warp per row

__device__ float g_partials[NBLK];

__global__ void __launch_bounds__(256)
center_loss_rows(const float* __restrict__ x,
                 const int*   __restrict__ labels,
                 const float* __restrict__ centers) {
    const int warp = threadIdx.x >> 5;
    const int lane = threadIdx.x & 31;
    const int row  = blockIdx.x * 8 + warp;   // 0..1023

    const int lab = labels[row];

    // 128 floats per row = 32 lanes * float4
    const float4 a = reinterpret_cast<const float4*>(x       + (size_t)row * FEAT)[lane];
    const float4 b = reinterpret_cast<const float4*>(centers + (size_t)lab * FEAT)[lane];

    const float d0 = a.x - b.x;
    const float d1 = a.y - b.y;
    const float d2 = a.z - b.z;
    const float d3 = a.w - b.w;
    float s = d0 * d0 + d1 * d1 + d2 * d2 + d3 * d3;

    // warp reduce -> full ||x - c||^2 for this row
    #pragma unroll
    for (int off = 16; off; off >>= 1)
        s += __shfl_xor_sync(0xffffffffu, s, off);

    // clamp (matches jnp.clip on the surviving diagonal entry)
    s = fminf(fmaxf(s, 1e-12f), 1e12f);

    // deterministic block reduce over the 8 warps
    __shared__ float sm[8];
    if (lane == 0) sm[warp] = s;
    __syncthreads();
    if (threadIdx.x == 0) {
        float t = 0.0f;
        #pragma unroll
        for (int i = 0; i < 8; i++) t += sm[i];
        g_partials[blockIdx.x] = t;
    }
}

__global__ void __launch_bounds__(32)
center_loss_final(float* __restrict__ out) {
    const int lane = threadIdx.x;
    float s = g_partials[lane] + g_partials[lane + 32]
            + g_partials[lane + 64] + g_partials[lane + 96];
    #pragma unroll
    for (int off = 16; off; off >>= 1)
        s += __shfl_xor_sync(0xffffffffu, s, off);
    if (lane == 0) {
        // (B*C - B) masked zeros, each clamped up to 1e-12
        const double extra = (double)((long long)BATCH * (long long)NUM_CLASS
                                      - (long long)BATCH) * 1e-12;
        out[0] = (float)(((double)s + extra) / (double)BATCH);
    }
}

extern "C" void kernel_launch(void* const* d_in, const int* in_sizes, int n_in,
                              void* d_out, int out_size) {
    const float* x       = (const float*)d_in[0];
    const int*   labels  = (const int*)  d_in[1];
    const float* centers = (const float*)d_in[2];
    float*       out     = (float*)d_out;

    center_loss_rows<<<NBLK, 256>>>(x, labels, centers);
    center_loss_final<<<1, 32>>>(out);
}